// round 14
// baseline (speedup 1.0000x reference)
#include <cuda_runtime.h>
#include <math.h>
#include <stdint.h>

// ---------------- problem constants ----------------
constexpr int T_    = 64;
constexpr int B_    = 32;
constexpr int D_    = 1024;
constexpr int L_    = 2;
constexpr int MEM_  = 35;
constexpr int NTOK_ = 32000;
constexpr int DK_   = 512;         // D / HEADS
constexpr int MB_   = MEM_ * B_;   // 1120
constexpr int BD_   = B_ * D_;     // 32768
constexpr float EPS_   = 1e-6f;
constexpr float SCALE_ = 0.04419417382415922f;  // 1/sqrt(512)

constexpr int NB_   = 296;         // persistent grid: 2 CTAs/SM on 148 SMs
constexpr int GAV_  = 10;
constexpr int MTILE_ = 112;        // 1120 / 10

constexpr int NDEC_   = (NTOK_ / 16);          // 2000 decoder n-tiles per step
constexpr int DEC_TOT = T_ * NDEC_;            // 128000 decoder tiles

// output layout (floats): decoded, h, c, H, C
constexpr long long OFF_DEC = 0;
constexpr long long SZ_DEC  = (long long)T_ * B_ * NTOK_;
constexpr long long OFF_H   = OFF_DEC + SZ_DEC;
constexpr long long SZ_HC   = (long long)L_ * B_ * D_;
constexpr long long OFF_C   = OFF_H + SZ_HC;
constexpr long long OFF_HM  = OFF_C + SZ_HC;
constexpr long long SZ_HM   = (long long)L_ * MEM_ * B_ * D_;
constexpr long long OFF_CM  = OFF_HM + SZ_HM;
constexpr long long TOTAL_OUT = OFF_CM + SZ_HM;

// ---------------- device scratch (static; no allocation) ----------------
__device__ float g_e[BD_];
__device__ float g_ln[BD_];
__device__ float g_q[BD_];
__device__ float g_Kc[MEM_ * BD_];
__device__ float g_Vc[MEM_ * BD_];
__device__ float g_sc[2 * B_ * MB_];        // [(h*32+b)][1120]
__device__ float g_attp[GAV_ * BD_];
__device__ float g_att[BD_];
__device__ float g_hsum[L_ * BD_];
__device__ float g_h[L_ * BD_];
__device__ float g_c[L_ * BD_];
__device__ float g_gp[2 * B_ * 4 * D_];     // gate partials [m=ih/hh][b][4096]
__device__ float g_xs[(long long)T_ * BD_];

__device__ unsigned g_bcount = 0;
__device__ volatile unsigned g_bgen = 0;
__device__ int g_pctr[4];                   // per-phase task counters (ring)
__device__ int g_dec = 0;                   // decoder filler counter

__device__ __forceinline__ float sigm(float x) { return 1.f / (1.f + expf(-x)); }

// ---------------- global barrier; master resets NEXT phase's counter ------
__device__ __forceinline__ void gbar(int nextph) {
    __syncthreads();
    if (threadIdx.x == 0) {
        unsigned gen = g_bgen;
        __threadfence();
        if (atomicAdd(&g_bcount, 1u) == NB_ - 1) {
            g_bcount = 0;
            g_pctr[nextph & 3] = 0;
            __threadfence();
            g_bgen = gen + 1;
        } else {
            while (g_bgen == gen) __nanosleep(32);
            __threadfence();
        }
    }
    __syncthreads();
}

// ---------------- 32b x 16n tile GEMM, full-K accumulate ----------------
__device__ __forceinline__ void tile16(const float* __restrict__ A, int lda,
                                       const float* __restrict__ W, int ldw,
                                       int K, float* sA, float* sW, float acc[4]) {
    int tid = threadIdx.x;
    int c4  = (tid & 7) * 4;
    int ar0 = tid >> 3;
    int ar1 = 16 + ar0;
    int wr  = tid >> 3;
    const float* Ap0 = A + (size_t)ar0 * lda + c4;
    const float* Ap1 = A + (size_t)ar1 * lda + c4;
    const float* Wp  = W + (size_t)wr  * ldw + c4;
    int o  = tid & 15;
    int b0 = (tid >> 4) * 4;
    float4 a0 = *(const float4*)Ap0;
    float4 a1 = *(const float4*)Ap1;
    float4 w0 = *(const float4*)Wp;
    for (int kc = 0; kc < K; kc += 32) {
        __syncthreads();
        *(float4*)&sA[ar0 * 44 + c4] = a0;
        *(float4*)&sA[ar1 * 44 + c4] = a1;
        *(float4*)&sW[wr  * 44 + c4] = w0;
        __syncthreads();
        if (kc + 32 < K) {
            a0 = *(const float4*)(Ap0 + kc + 32);
            a1 = *(const float4*)(Ap1 + kc + 32);
            w0 = *(const float4*)(Wp  + kc + 32);
        }
#pragma unroll
        for (int kk = 0; kk < 8; kk++) {
            float4 w = *(const float4*)&sW[o * 44 + kk * 4];
#pragma unroll
            for (int i = 0; i < 4; i++) {
                float4 a = *(const float4*)&sA[(b0 + i) * 44 + kk * 4];
                acc[i] += a.x * w.x + a.y * w.y + a.z * w.z + a.w * w.w;
            }
        }
    }
}

// ---------------- decoder filler tile ----------------
__device__ __forceinline__ void dec_fill(int d, const float* __restrict__ dec_W,
                                         const float* __restrict__ dec_b,
                                         float* __restrict__ out,
                                         float* sA, float* sW) {
    int tt = d / NDEC_;
    int n0 = (d % NDEC_) * 16;
    float acc[4] = {};
    tile16(g_xs + (size_t)tt * BD_, D_, dec_W + (size_t)n0 * D_, D_, D_, sA, sW, acc);
    int tid = threadIdx.x;
    int o = tid & 15;
    int b0 = (tid >> 4) * 4;
    float bb = dec_b[n0 + o];
#pragma unroll
    for (int i = 0; i < 4; i++)
        out[OFF_DEC + (size_t)(tt * B_ + b0 + i) * NTOK_ + n0 + o] = acc[i] + bb;
}

// ---------------- phase runner: work-steal + decoder fillers ----------------
// body(i) is a block-uniform lambda; stolen index broadcast via smem.
template <class F>
__device__ __forceinline__ void run_phase(int nt, int dlim, int& ph, int* s_task,
                                          const float* dec_W, const float* dec_b,
                                          float* out, float* sA, float* sW, F&& body) {
    int tid = threadIdx.x;
    int quota = (nt + NB_ - 1) / NB_;
    int taken = 0;
    for (;;) {
        if (tid == 0) *s_task = atomicAdd(&g_pctr[ph & 3], 1);
        __syncthreads();
        int i = *s_task;
        __syncthreads();
        if (i >= nt) break;
        body(i);
        taken++;
    }
    for (int f = taken; f < quota; f++) {
        if (tid == 0) {
            int dd = -1;
            for (;;) {
                int cur = *(volatile int*)&g_dec;
                if (cur >= dlim) break;
                if (atomicCAS(&g_dec, cur, cur + 1) == cur) { dd = cur; break; }
            }
            *s_task = dd;
        }
        __syncthreads();
        int d = *s_task;
        __syncthreads();
        if (d < 0) break;
        dec_fill(d, dec_W, dec_b, out, sA, sW);
    }
    ph++;
    gbar(ph);
}

// ---------------- init: carry state + counters ----------------
__global__ void k_init_state(const float* __restrict__ h0, const float* __restrict__ c0) {
    int i = blockIdx.x * blockDim.x + threadIdx.x;
    if (i < L_ * BD_) { g_h[i] = h0[i]; g_c[i] = c0[i]; }
    if (i < 4) g_pctr[i] = 0;
    if (i == 0) { g_dec = 0; g_bcount = 0; g_bgen = 0; }
}

// ---------------- tiled SGEMM (cache init only) ----------------
__global__ __launch_bounds__(256, 2)
void k_gemm(const float* __restrict__ A, const float* __restrict__ W,
            const float* __restrict__ bias, int csel,
            int M, int N, int K) {
    float* C = (csel == 0) ? g_Kc : g_Vc;
    __shared__ __align__(16) float As[8][128];
    __shared__ __align__(16) float Bs[8][128];
    int m0 = blockIdx.x * 128, n0 = blockIdx.y * 128;
    int tid = threadIdx.x;
    int tr = tid / 16, tc = tid % 16;
    int lr = tid / 2, lk = (tid % 2) * 4;
    float acc[8][8];
#pragma unroll
    for (int i = 0; i < 8; i++)
#pragma unroll
        for (int j = 0; j < 8; j++) acc[i][j] = 0.f;
    for (int k0 = 0; k0 < K; k0 += 8) {
        float4 av = make_float4(0,0,0,0), bv = make_float4(0,0,0,0);
        if (m0 + lr < M) av = *(const float4*)&A[(size_t)(m0 + lr) * K + k0 + lk];
        if (n0 + lr < N) bv = *(const float4*)&W[(size_t)(n0 + lr) * K + k0 + lk];
        __syncthreads();
        As[lk+0][lr] = av.x; As[lk+1][lr] = av.y; As[lk+2][lr] = av.z; As[lk+3][lr] = av.w;
        Bs[lk+0][lr] = bv.x; Bs[lk+1][lr] = bv.y; Bs[lk+2][lr] = bv.z; Bs[lk+3][lr] = bv.w;
        __syncthreads();
#pragma unroll
        for (int k = 0; k < 8; k++) {
            float af[8], bf[8];
            *(float4*)&af[0] = *(const float4*)&As[k][tr * 4];
            *(float4*)&af[4] = *(const float4*)&As[k][64 + tr * 4];
            *(float4*)&bf[0] = *(const float4*)&Bs[k][tc * 4];
            *(float4*)&bf[4] = *(const float4*)&Bs[k][64 + tc * 4];
#pragma unroll
            for (int i = 0; i < 8; i++)
#pragma unroll
                for (int j = 0; j < 8; j++) acc[i][j] += af[i] * bf[j];
        }
    }
    int rb[2] = { m0 + tr * 4, m0 + 64 + tr * 4 };
    int cb[2] = { n0 + tc * 4, n0 + 64 + tc * 4 };
#pragma unroll
    for (int ih = 0; ih < 2; ih++)
#pragma unroll
        for (int i = 0; i < 4; i++) {
            int m = rb[ih] + i;
            if (m >= M) continue;
#pragma unroll
            for (int jh = 0; jh < 2; jh++)
#pragma unroll
                for (int j = 0; j < 4; j++) {
                    int n = cb[jh] + j;
                    if (n < N) C[(size_t)m * N + n] = acc[ih*4+i][jh*4+j] + bias[n];
                }
        }
}

// ---------------- persistent step-loop kernel ----------------
__global__ __launch_bounds__(128, 2)
void k_steps(const int* __restrict__ tokens, const float* __restrict__ emb,
             const float* __restrict__ lng, const float* __restrict__ lnb,
             const float* __restrict__ Wq, const float* __restrict__ bq,
             const float* __restrict__ Wk, const float* __restrict__ bk,
             const float* __restrict__ Wv, const float* __restrict__ bv,
             const float* __restrict__ Wo, const float* __restrict__ bo,
             const float* __restrict__ Wih, const float* __restrict__ bih,
             const float* __restrict__ Whh, const float* __restrict__ bhh,
             const float* __restrict__ dec_W, const float* __restrict__ dec_b,
             float* __restrict__ out, int full) {
    __shared__ __align__(16) float sbuf[3584];    // 14 KB
    __shared__ float red1[4], red2[4];
    __shared__ int s_task;
    float* sA = sbuf;
    float* sW = sbuf + 1408;
    int bid = blockIdx.x, tid = threadIdx.x;
    int wid = tid >> 5, lid = tid & 31;
    int ph = 0;

    for (int t = 0; t < T_; t++) {
        int dlim = t * NDEC_;

        // ---- Ph: embed + LayerNorm (32) ----
        run_phase(B_, dlim, ph, &s_task, dec_W, dec_b, out, sA, sW, [&](int _i) {
            int b = _i;
            int tok = tokens[t * B_ + b];
            const float* er = emb + (size_t)tok * D_;
            float4 v0 = *(const float4*)(er + tid * 8);
            float4 v1 = *(const float4*)(er + tid * 8 + 4);
            float s  = v0.x+v0.y+v0.z+v0.w + v1.x+v1.y+v1.z+v1.w;
            float s2 = v0.x*v0.x+v0.y*v0.y+v0.z*v0.z+v0.w*v0.w
                     + v1.x*v1.x+v1.y*v1.y+v1.z*v1.z+v1.w*v1.w;
#pragma unroll
            for (int o = 16; o; o >>= 1) {
                s  += __shfl_xor_sync(~0u, s,  o);
                s2 += __shfl_xor_sync(~0u, s2, o);
            }
            if (lid == 0) { red1[wid] = s; red2[wid] = s2; }
            __syncthreads();
            float S  = red1[0]+red1[1]+red1[2]+red1[3];
            float S2 = red2[0]+red2[1]+red2[2]+red2[3];
            float mu  = S / D_;
            float var = (S2 - (float)D_ * mu * mu) / (float)(D_ - 1);
            float inv = 1.f / (sqrtf(fmaxf(var, 0.f)) + EPS_);
            float4 g0 = *(const float4*)(lng + tid * 8);
            float4 g1 = *(const float4*)(lng + tid * 8 + 4);
            float4 bb0 = *(const float4*)(lnb + tid * 8);
            float4 bb1 = *(const float4*)(lnb + tid * 8 + 4);
            size_t base = (size_t)b * D_ + tid * 8;
            *(float4*)&g_e[base]     = v0;
            *(float4*)&g_e[base + 4] = v1;
            float4 n0v = make_float4(g0.x*(v0.x-mu)*inv + bb0.x, g0.y*(v0.y-mu)*inv + bb0.y,
                                     g0.z*(v0.z-mu)*inv + bb0.z, g0.w*(v0.w-mu)*inv + bb0.w);
            float4 n1v = make_float4(g1.x*(v1.x-mu)*inv + bb1.x, g1.y*(v1.y-mu)*inv + bb1.y,
                                     g1.z*(v1.z-mu)*inv + bb1.z, g1.w*(v1.w-mu)*inv + bb1.w);
            *(float4*)&g_ln[base]     = n0v;
            *(float4*)&g_ln[base + 4] = n1v;
            __syncthreads();
        });

        // ---- Ph: q/k/v projections (192; 64 at t=0) ----
        run_phase((t == 0) ? 64 : 192, dlim, ph, &s_task, dec_W, dec_b, out, sA, sW, [&](int _i) {
            int sel = _i >> 6;
            int n0 = (_i & 63) * 16;
            const float* A; const float* W; const float* bias; float* C;
            if (sel == 0) { A = g_ln; W = Wq; bias = bq; C = g_q; }
            else {
                int slot = (t - 1) % MEM_;
                A = g_h;   // layer0 h from step t-1
                if (sel == 1) { W = Wk; bias = bk; C = g_Kc + (size_t)slot * BD_; }
                else          { W = Wv; bias = bv; C = g_Vc + (size_t)slot * BD_; }
            }
            float acc[4] = {};
            tile16(A, D_, W + (size_t)n0 * D_, D_, D_, sA, sW, acc);
            int o = tid & 15;
            int b0 = (tid >> 4) * 4;
            float bvv = bias[n0 + o];
#pragma unroll
            for (int i = 0; i < 4; i++)
                C[(size_t)(b0 + i) * D_ + n0 + o] = acc[i] + bvv;
        });

        // ---- Ph: scores (140) ----
        run_phase(140, dlim, ph, &s_task, dec_W, dec_b, out, sA, sW, [&](int _i) {
            int h = _i / 70;
            int m0 = (_i % 70) * 16;
            float acc[4] = {};
            tile16(g_q + h * DK_, D_, g_Kc + (size_t)m0 * D_ + h * DK_, D_, DK_, sA, sW, acc);
            int o = tid & 15;
            int b0 = (tid >> 4) * 4;
#pragma unroll
            for (int i = 0; i < 4; i++)
                g_sc[(size_t)(h * B_ + b0 + i) * MB_ + m0 + o] = acc[i] * SCALE_;
        });

        // ---- Ph: softmax (64) ----
        run_phase(64, dlim, ph, &s_task, dec_W, dec_b, out, sA, sW, [&](int _i) {
            float* row = g_sc + (size_t)_i * MB_;
            float mx = -1e30f;
            for (int i = tid; i < MB_; i += 128) mx = fmaxf(mx, row[i]);
#pragma unroll
            for (int o = 16; o; o >>= 1) mx = fmaxf(mx, __shfl_xor_sync(~0u, mx, o));
            if (lid == 0) red1[wid] = mx;
            __syncthreads();
            mx = fmaxf(fmaxf(red1[0], red1[1]), fmaxf(red1[2], red1[3]));
            __syncthreads();
            float s = 0.f;
            for (int i = tid; i < MB_; i += 128) { float e = expf(row[i] - mx); row[i] = e; s += e; }
#pragma unroll
            for (int o = 16; o; o >>= 1) s += __shfl_xor_sync(~0u, s, o);
            if (lid == 0) red2[wid] = s;
            __syncthreads();
            float inv = 1.f / (red2[0]+red2[1]+red2[2]+red2[3]);
            for (int i = tid; i < MB_; i += 128) row[i] *= inv;
            __syncthreads();
        });

        // ---- Ph: AV partials (80) ----
        run_phase(8 * GAV_, dlim, ph, &s_task, dec_W, dec_b, out, sA, sW, [&](int _i) {
            int gx = _i & 7;
            int gy = _i >> 3;
            float (*sw)[B_] = (float (*)[B_])sbuf;
            int d = gx * 128 + tid;
            int h = d >> 9;
            int m0 = gy * MTILE_;
            __syncthreads();
            for (int idx = tid; idx < MTILE_ * B_; idx += 128) {
                int mm = idx >> 5;
                int bb = idx & 31;
                sw[mm][bb] = g_sc[(size_t)(h * B_ + bb) * MB_ + m0 + mm];
            }
            __syncthreads();
            float acc[B_];
#pragma unroll
            for (int i = 0; i < B_; i++) acc[i] = 0.f;
#pragma unroll 4
            for (int mm = 0; mm < MTILE_; mm++) {
                float v = g_Vc[(size_t)(m0 + mm) * D_ + d];
                const float4* w4 = (const float4*)sw[mm];
#pragma unroll
                for (int q = 0; q < 8; q++) {
                    float4 w = w4[q];
                    acc[q*4+0] += w.x * v; acc[q*4+1] += w.y * v;
                    acc[q*4+2] += w.z * v; acc[q*4+3] += w.w * v;
                }
            }
            float* dst = g_attp + (size_t)gy * BD_;
#pragma unroll
            for (int bb = 0; bb < B_; bb++) dst[bb * D_ + d] = acc[bb];
            __syncthreads();
        });

        // ---- Ph: reduce partials (32) ----
        run_phase(32, dlim, ph, &s_task, dec_W, dec_b, out, sA, sW, [&](int _i) {
#pragma unroll
            for (int k = 0; k < 8; k++) {
                int j = _i * 1024 + k * 128 + tid;
                float s = g_attp[j];
#pragma unroll
                for (int g = 1; g < GAV_; g++) s += g_attp[(size_t)g * BD_ + j];
                g_att[j] = s;
            }
        });

        // ---- Ph: O-proj + residuals -> hsum (64) ----
        run_phase(64, dlim, ph, &s_task, dec_W, dec_b, out, sA, sW, [&](int _i) {
            int n0 = _i * 16;
            float acc[4] = {};
            tile16(g_att, D_, Wo + (size_t)n0 * D_, D_, D_, sA, sW, acc);
            int o = tid & 15;
            int b0 = (tid >> 4) * 4;
            float bov = bo[n0 + o];
#pragma unroll
            for (int i = 0; i < 4; i++) {
                size_t idx = (size_t)(b0 + i) * D_ + n0 + o;
                float ha = acc[i] + bov + g_e[idx];
                g_hsum[idx]       = ha + g_h[idx];
                g_hsum[BD_ + idx] = ha + g_h[BD_ + idx];
            }
        });

        // ---- LSTM layers ----
        for (int l = 0; l < L_; l++) {
            // gates GEMM: 512 tasks = {ih, hh} x 256 n-tiles, K=1024
            run_phase(512, dlim, ph, &s_task, dec_W, dec_b, out, sA, sW, [&](int _i) {
                int m = _i >> 8;
                int n0 = (_i & 255) * 16;
                const float* A = m ? (g_hsum + (size_t)l * BD_)
                                   : ((l == 0) ? g_e : g_h);
                const float* W = (m ? Whh : Wih) + ((size_t)l * 4 * D_ + n0) * D_;
                float acc[4] = {};
                tile16(A, D_, W, D_, D_, sA, sW, acc);
                int o = tid & 15;
                int b0 = (tid >> 4) * 4;
                float* dst = g_gp + (size_t)m * B_ * 4 * D_;
#pragma unroll
                for (int i = 0; i < 4; i++)
                    dst[(size_t)(b0 + i) * 4 * D_ + n0 + o] = acc[i];
            });

            // elementwise (32)
            run_phase(32, dlim, ph, &s_task, dec_W, dec_b, out, sA, sW, [&](int _i) {
#pragma unroll
                for (int k = 0; k < 8; k++) {
                    int i = _i * 1024 + k * 128 + tid;
                    int b = i >> 10;
                    int o = i & 1023;
                    size_t gb = (size_t)b * 4 * D_;
                    size_t g2 = (size_t)B_ * 4 * D_ + gb;
                    int jb = l * 4 * D_;
                    float ig = g_gp[gb + o]        + g_gp[g2 + o]        + bih[jb + o]        + bhh[jb + o];
                    float fg = g_gp[gb + D_ + o]   + g_gp[g2 + D_ + o]   + bih[jb + D_ + o]   + bhh[jb + D_ + o];
                    float gg = g_gp[gb + 2*D_ + o] + g_gp[g2 + 2*D_ + o] + bih[jb + 2*D_ + o] + bhh[jb + 2*D_ + o];
                    float og = g_gp[gb + 3*D_ + o] + g_gp[g2 + 3*D_ + o] + bih[jb + 3*D_ + o] + bhh[jb + 3*D_ + o];
                    float c_old = g_c[l * BD_ + i];
                    float cn = sigm(fg) * c_old + sigm(ig) * tanhf(gg);
                    float hn = sigm(og) * tanhf(cn);
                    g_c[l * BD_ + i] = cn;
                    g_h[l * BD_ + i] = hn;
                    if (l == L_ - 1) g_xs[(size_t)t * BD_ + i] = hn;
                    if (full && t >= T_ - MEM_) {
                        long long j = t - (T_ - MEM_);
                        out[OFF_HM + (((long long)l * MEM_ + j) * B_ + b) * D_ + o] = hn;
                        out[OFF_CM + (((long long)l * MEM_ + j) * B_ + b) * D_ + o] = cn;
                    }
                }
            });
        }
    }

    // ---- final h,c copy (g_h/g_c final after last barrier) ----
    if (full) {
        for (int i = bid; i < 16; i += NB_) {
#pragma unroll
            for (int k = 0; k < 32; k++) {
                int idx = i * 4096 + k * 128 + tid;
                out[OFF_H + idx] = g_h[idx];
                out[OFF_C + idx] = g_c[idx];
            }
        }
    }

    // ---- drain remaining decoder tiles ----
    for (;;) {
        if (tid == 0) s_task = atomicAdd(&g_dec, 1);
        __syncthreads();
        int d = s_task;
        __syncthreads();
        if (d >= DEC_TOT) break;
        dec_fill(d, dec_W, dec_b, out, sA, sW);
    }
}

// ---------------- host launch ----------------
extern "C" void kernel_launch(void* const* d_in, const int* in_sizes, int n_in,
                              void* d_out, int out_size) {
    const int*   tokens = (const int*)  d_in[0];
    const float* emb    = (const float*)d_in[1];
    const float* ln_g   = (const float*)d_in[2];
    const float* ln_b   = (const float*)d_in[3];
    const float* Wq     = (const float*)d_in[4];
    const float* bq     = (const float*)d_in[5];
    const float* Wk     = (const float*)d_in[6];
    const float* bk     = (const float*)d_in[7];
    const float* Wv     = (const float*)d_in[8];
    const float* bv     = (const float*)d_in[9];
    const float* Wo     = (const float*)d_in[10];
    const float* bo     = (const float*)d_in[11];
    const float* W_ih   = (const float*)d_in[12];
    const float* b_ih   = (const float*)d_in[13];
    const float* W_hh   = (const float*)d_in[14];
    const float* b_hh   = (const float*)d_in[15];
    const float* dec_W  = (const float*)d_in[16];
    const float* dec_b  = (const float*)d_in[17];
    const float* h0     = (const float*)d_in[18];
    const float* c0     = (const float*)d_in[19];
    const float* H0     = (const float*)d_in[20];
    float* out = (float*)d_out;
    int full = (out_size >= (int)TOTAL_OUT) ? 1 : 0;

    k_init_state<<<(L_ * BD_ + 255) / 256, 256>>>(h0, c0);

    // K/V cache init from H0[0]  (M=1120, N=1024, K=1024)
    dim3 gi((MB_ + 127) / 128, D_ / 128);
    k_gemm<<<gi, 256>>>(H0, Wk, bk, 0, MB_, D_, D_);
    k_gemm<<<gi, 256>>>(H0, Wv, bv, 1, MB_, D_, D_);

    // whole recurrence + decoder (as filler work) in one persistent kernel
    k_steps<<<NB_, 128>>>(tokens, emb, ln_g, ln_b, Wq, bq, Wk, bk, Wv, bv,
                          Wo, bo, W_ih, b_ih, W_hh, b_hh, dec_W, dec_b, out, full);
}